// round 1
// baseline (speedup 1.0000x reference)
#include <cuda_runtime.h>
#include <cuda_bf16.h>

// AutocorrelationCorrelogram on GB300.
// Input : nervegram (4, 50, 20000, 2) fp32  -> read as float2 (ch0 = .x, ch1 = .y)
// Output: (4, 50, 300, 256) fp32
//
// Per (b,f,frame): z[n] = (ch0, ch1) windowed -> one 512-pt complex DIF FFT
// (natural in, bit-reversed out). Hermitian split recovers both channel
// spectra; Q[k] = |A[k]|^2 + i*|B[k]|^2 (both real-even) -> one 512-pt
// complex DIT inverse FFT (bit-reversed in, natural out) yields
// acf0[n] + i*acf1[n]. Then relu, per-channel 1/sqrt(acf[0]) norm (0 -> 1),
// keep lags 0..255, average channels.

#define PI_F 3.14159265358979323846f

__device__ __forceinline__ int bitrev9(int x) {
    return (int)(__brev((unsigned)x) >> 23);
}

__global__ void __launch_bounds__(256)
acf_kernel(const float2* __restrict__ in, float* __restrict__ out) {
    __shared__ float2 A[512];    // forward FFT workspace
    __shared__ float2 Bq[512];   // Q / inverse FFT workspace
    __shared__ float2 W[256];    // twiddles: W[m] = exp(-2*pi*i*m/512)

    const int t     = threadIdx.x;   // 0..255
    const int frame = blockIdx.x;    // 0..299
    const int bf    = blockIdx.y;    // 0..199  (b*50 + f)

    // Twiddle table (forward sign; inverse uses conj).
    {
        float s, c;
        sincosf(-2.0f * PI_F * (float)t / 512.0f, &s, &c);
        W[t] = make_float2(c, s);
    }

    // Frame start, matching np.linspace(0, 19488, 300).astype(int64).
    const long start = (long)(19488.0 * (double)frame / 299.0);
    const float2* src = in + ((long)bf * 20000 + start);

    // Coalesced load + Hann window, natural order.
#pragma unroll
    for (int i = 0; i < 2; i++) {
        const int n = t + i * 256;
        const float w = 0.5f - 0.5f * cosf(2.0f * PI_F * (float)n / 512.0f);
        const float2 v = src[n];
        A[n] = make_float2(v.x * w, v.y * w);
    }
    __syncthreads();

    // ---- Forward FFT: radix-2 DIF, natural in -> bit-reversed out ----
#pragma unroll
    for (int hb = 8; hb >= 0; hb--) {
        const int half = 1 << hb;
        const int j  = t & (half - 1);
        const int i0 = ((t >> hb) << (hb + 1)) + j;
        const int i1 = i0 + half;
        const float2 u = A[i0];
        const float2 v = A[i1];
        const float2 w = W[j << (8 - hb)];
        const float dx = u.x - v.x, dy = u.y - v.y;
        A[i0] = make_float2(u.x + v.x, u.y + v.y);
        A[i1] = make_float2(dx * w.x - dy * w.y, dx * w.y + dy * w.x);
        __syncthreads();
    }

    // ---- Hermitian split + power spectra, in the bit-reversed domain ----
    // Position j holds F[k], k = bitrev9(j). Need F[(512-k)%512] at jj.
#pragma unroll
    for (int i = 0; i < 2; i++) {
        const int j  = t + i * 256;
        const int k  = bitrev9(j);
        const int kk = (512 - k) & 511;
        const int jj = bitrev9(kk);
        const float2 Fk = A[j];
        const float2 Fm = A[jj];
        // A[k] = (F[k] + conj(F[-k]))/2   (spectrum of ch0)
        const float ax = 0.5f * (Fk.x + Fm.x);
        const float ay = 0.5f * (Fk.y - Fm.y);
        // B[k] = (F[k] - conj(F[-k]))/(2i) (spectrum of ch1)
        const float bx = 0.5f * (Fk.y + Fm.y);
        const float by = -0.5f * (Fk.x - Fm.x);
        const float p0 = ax * ax + ay * ay;
        const float p1 = bx * bx + by * by;
        Bq[j] = make_float2(p0, p1);   // Q[k] = P0[k] + i*P1[k], stored bit-reversed
    }
    __syncthreads();

    // ---- Inverse FFT: radix-2 DIT, bit-reversed in -> natural out ----
#pragma unroll
    for (int hb = 0; hb <= 8; hb++) {
        const int half = 1 << hb;
        const int j  = t & (half - 1);
        const int i0 = ((t >> hb) << (hb + 1)) + j;
        const int i1 = i0 + half;
        const float2 u = Bq[i0];
        const float2 v = Bq[i1];
        const float2 w = W[j << (8 - hb)];   // conj(w) for inverse
        const float vwx = v.x * w.x + v.y * w.y;
        const float vwy = v.y * w.x - v.x * w.y;
        Bq[i0] = make_float2(u.x + vwx, u.y + vwy);
        Bq[i1] = make_float2(u.x - vwx, u.y - vwy);
        __syncthreads();
    }

    // ---- relu, per-channel normalization, channel mean, write lags 0..255 ----
    const float inv = 1.0f / 512.0f;   // irfft scaling (does NOT cancel in norm)
    const float2 q0 = Bq[0];
    const float n0 = fmaxf(q0.x * inv, 0.0f);
    const float n1 = fmaxf(q0.y * inv, 0.0f);
    const float s0 = (n0 == 0.0f) ? 1.0f : rsqrtf(n0);
    const float s1 = (n1 == 0.0f) ? 1.0f : rsqrtf(n1);

    const float2 qk = Bq[t];
    const float a0 = fmaxf(qk.x * inv, 0.0f) * s0;
    const float a1 = fmaxf(qk.y * inv, 0.0f) * s1;

    out[((long)bf * 300 + frame) * 256 + t] = 0.5f * (a0 + a1);
}

extern "C" void kernel_launch(void* const* d_in, const int* in_sizes, int n_in,
                              void* d_out, int out_size) {
    const float2* in = (const float2*)d_in[0];  // (4,50,20000,2) fp32 -> float2[4*50*20000]
    float* out = (float*)d_out;                 // (4,50,300,256) fp32
    dim3 grid(300, 200, 1);                     // frame, b*50+f
    acf_kernel<<<grid, 256>>>(in, out);
}

// round 2
// speedup vs baseline: 3.9694x; 3.9694x over previous
#include <cuda_runtime.h>
#include <cuda_bf16.h>

// Register-resident 512-pt FFT (radix 8x8x8): 64 threads/FFT, 8 complex/thread.
// 3 register radix-8 stages + 2 smem transposes per FFT direction.
// Channels packed as one complex signal; power spectra packed as Q = P0 + i*P1
// so one complex inverse FFT yields both channels' ACFs.

#define TPI_512 0.012271846303085130f   // 2*pi/512
#define TPI_64  0.098174770424681038f   // 2*pi/64

__device__ __forceinline__ float2 cmul(float2 a, float2 b) {
    return make_float2(fmaf(a.x, b.x, -a.y * b.y), fmaf(a.x, b.y, a.y * b.x));
}

template<int SGN>   // -1 = forward (e^{-i}), +1 = inverse (e^{+i})
__device__ __forceinline__ void radix8(float2 x[8]) {
    const float C = 0.70710678118654752440f;
    float2 t0 = make_float2(x[0].x + x[4].x, x[0].y + x[4].y);
    float2 t4 = make_float2(x[0].x - x[4].x, x[0].y - x[4].y);
    float2 t1 = make_float2(x[1].x + x[5].x, x[1].y + x[5].y);
    float2 t5 = make_float2(x[1].x - x[5].x, x[1].y - x[5].y);
    float2 t2 = make_float2(x[2].x + x[6].x, x[2].y + x[6].y);
    float2 t6 = make_float2(x[2].x - x[6].x, x[2].y - x[6].y);
    float2 t3 = make_float2(x[3].x + x[7].x, x[3].y + x[7].y);
    float2 t7 = make_float2(x[3].x - x[7].x, x[3].y - x[7].y);
    if (SGN < 0) {
        t5 = make_float2(C * (t5.x + t5.y), C * (t5.y - t5.x));   // * (c - ic)
        t6 = make_float2(t6.y, -t6.x);                            // * -i
        t7 = make_float2(C * (t7.y - t7.x), -C * (t7.x + t7.y));  // * (-c - ic)
    } else {
        t5 = make_float2(C * (t5.x - t5.y), C * (t5.x + t5.y));   // * (c + ic)
        t6 = make_float2(-t6.y, t6.x);                            // * +i
        t7 = make_float2(-C * (t7.x + t7.y), C * (t7.x - t7.y));  // * (-c + ic)
    }
    float2 u0 = make_float2(t0.x + t2.x, t0.y + t2.y);
    float2 u2 = make_float2(t0.x - t2.x, t0.y - t2.y);
    float2 u1 = make_float2(t1.x + t3.x, t1.y + t3.y);
    float2 u3 = make_float2(t1.x - t3.x, t1.y - t3.y);
    u3 = (SGN < 0) ? make_float2(u3.y, -u3.x) : make_float2(-u3.y, u3.x);
    x[0] = make_float2(u0.x + u1.x, u0.y + u1.y);
    x[4] = make_float2(u0.x - u1.x, u0.y - u1.y);
    x[2] = make_float2(u2.x + u3.x, u2.y + u3.y);
    x[6] = make_float2(u2.x - u3.x, u2.y - u3.y);
    float2 v0 = make_float2(t4.x + t6.x, t4.y + t6.y);
    float2 v2 = make_float2(t4.x - t6.x, t4.y - t6.y);
    float2 v1 = make_float2(t5.x + t7.x, t5.y + t7.y);
    float2 v3 = make_float2(t5.x - t7.x, t5.y - t7.y);
    v3 = (SGN < 0) ? make_float2(v3.y, -v3.x) : make_float2(-v3.y, v3.x);
    x[1] = make_float2(v0.x + v1.x, v0.y + v1.y);
    x[5] = make_float2(v0.x - v1.x, v0.y - v1.y);
    x[3] = make_float2(v2.x + v3.x, v2.y + v3.y);
    x[7] = make_float2(v2.x - v3.x, v2.y - v3.y);
}

// x[k] *= w^k, k=1..7, via log-depth power tree.
__device__ __forceinline__ void twiddle7(float2 x[8], float2 w) {
    float2 w2 = cmul(w, w);
    float2 w3 = cmul(w2, w);
    float2 w4 = cmul(w2, w2);
    float2 w5 = cmul(w2, w3);
    float2 w6 = cmul(w3, w3);
    float2 w7 = cmul(w3, w4);
    x[1] = cmul(x[1], w);  x[2] = cmul(x[2], w2); x[3] = cmul(x[3], w3);
    x[4] = cmul(x[4], w4); x[5] = cmul(x[5], w5); x[6] = cmul(x[6], w6);
    x[7] = cmul(x[7], w7);
}

// Bank-conflict-free swizzled addressing (verified per half-warp, 8B elems):
// T1: holds y_{k1}[n2];  write (k1=reg, n2=t), read (k1=t>>3, n2=8a+b, b=t&7).
__device__ __forceinline__ int phys1(int k1, int n2) {
    return (k1 << 6) | (n2 ^ ((k1 & 1) << 3));
}
// T2: holds u_{k1,k1'}[b]; write (k1=t>>3, k1'=reg, b=t&7), read (k1=t>>3, k1'=t&7, b=reg).
__device__ __forceinline__ int phys2i(int k1, int k1p, int b) {
    return (k1 << 6) | ((k1p >> 1) << 4) | (((k1 ^ k1p) & 1) << 3) | ((b ^ k1p) & 7);
}
// F natural-k store; write k = 64*k2 + 8*k1' + k1, read k = 64r + t (and 512-k).
__device__ __forceinline__ int physF(int k) {
    return k ^ (((k >> 4) & 3) << 1);
}

// 512-pt complex FFT across 64 threads. Input: x[r] = data[64r + t].
// Output: x[r] = F[(r<<6) + ((t&7)<<3) + (t>>3)].
// Contains 2 __syncthreads (all groups execute identically).
template<int SGN>
__device__ __forceinline__ void fft512(float2 x[8], int t, float2* bufT1, float2* bufT2) {
    radix8<SGN>(x);
    {
        float s, c;
        sincosf((float)SGN * TPI_512 * (float)t, &s, &c);
        twiddle7(x, make_float2(c, s));
    }
#pragma unroll
    for (int r = 0; r < 8; r++) bufT1[phys1(r, t)] = x[r];
    __syncthreads();
    const int k1 = t >> 3, b = t & 7;
#pragma unroll
    for (int a = 0; a < 8; a++) x[a] = bufT1[phys1(k1, (a << 3) | b)];
    radix8<SGN>(x);
    {
        float s, c;
        sincosf((float)SGN * TPI_64 * (float)b, &s, &c);
        twiddle7(x, make_float2(c, s));
    }
#pragma unroll
    for (int r = 0; r < 8; r++) bufT2[phys2i(k1, r, b)] = x[r];
    __syncthreads();
#pragma unroll
    for (int bb = 0; bb < 8; bb++) x[bb] = bufT2[phys2i(k1, b, bb)];  // here (t&7) plays k1'
    radix8<SGN>(x);
}

__global__ void __launch_bounds__(256)
acf_kernel(const float2* __restrict__ in, float* __restrict__ out) {
    __shared__ float2 SM[2][4 * 520];   // ping-pong buffers, 4 groups, 8-elem pad between

    const int tid   = threadIdx.x;
    const int g     = tid >> 6;        // FFT group 0..3
    const int t     = tid & 63;        // lane within FFT
    const int frame = blockIdx.x * 4 + g;
    const int bf    = blockIdx.y;

    float2* smA = &SM[0][g * 520];
    float2* smB = &SM[1][g * 520];

    // Frame start, matching np.linspace(0, 19488, 300).astype(int64).
    const long start = (long)(19488.0 * (double)frame / 299.0);
    const float2* src = in + ((long)bf * 20000 + start);

    // Load + Hann window: x[r] = z[64r + t], z = ch0 + i*ch1.
    float2 x[8];
#pragma unroll
    for (int r = 0; r < 8; r++) {
        const int n = (r << 6) + t;
        const float w = 0.5f - 0.5f * cosf(TPI_512 * (float)n);
        const float2 v = src[n];
        x[r] = make_float2(v.x * w, v.y * w);
    }

    // Forward FFT (2 internal barriers). Output: x[r] = F[k], k = 64r + 8*(t&7) + (t>>3).
    fft512<-1>(x, t, smA, smB);

    // Store F at natural k (smA reads finished before last barrier inside fft512).
    const int klo = ((t & 7) << 3) | (t >> 3);
#pragma unroll
    for (int r = 0; r < 8; r++) smA[physF((r << 6) + klo)] = x[r];
    __syncthreads();

    // Hermitian split + power spectra -> Q[k] directly into inverse-input layout:
    // x[r] = Q[64r + t].
#pragma unroll
    for (int r = 0; r < 8; r++) {
        const int k  = (r << 6) + t;
        const int kk = (512 - k) & 511;
        const float2 Fk = smA[physF(k)];
        const float2 Fm = smA[physF(kk)];
        const float ax = 0.5f * (Fk.x + Fm.x);
        const float ay = 0.5f * (Fk.y - Fm.y);
        const float bx = 0.5f * (Fk.y + Fm.y);
        const float by = -0.5f * (Fk.x - Fm.x);
        x[r] = make_float2(ax * ax + ay * ay, bx * bx + by * by);
    }

    // Inverse FFT. Output: x[c] = 512 * (acf0 + i*acf1)[n], n = 64c + 8*(t&7) + (t>>3).
    fft512<+1>(x, t, smB, smA);

    // Broadcast acf[0] (held by t==0, reg 0; smB reads long finished).
    if (t == 0) smB[512] = x[0];
    __syncthreads();

    const float inv = 1.0f / 512.0f;
    const float2 q0 = smB[512];
    const float n0 = fmaxf(q0.x * inv, 0.0f);
    const float n1 = fmaxf(q0.y * inv, 0.0f);
    const float s0 = (n0 == 0.0f) ? 1.0f : rsqrtf(n0);
    const float s1 = (n1 == 0.0f) ? 1.0f : rsqrtf(n1);

    float* op = out + ((long)bf * 300 + frame) * 256;
#pragma unroll
    for (int c = 0; c < 4; c++) {            // lags 0..255 <=> c < 4
        const float a0 = fmaxf(x[c].x * inv, 0.0f) * s0;
        const float a1 = fmaxf(x[c].y * inv, 0.0f) * s1;
        op[(c << 6) + klo] = 0.5f * (a0 + a1);
    }
}

extern "C" void kernel_launch(void* const* d_in, const int* in_sizes, int n_in,
                              void* d_out, int out_size) {
    const float2* in = (const float2*)d_in[0];  // (4,50,20000,2) fp32 as float2
    float* out = (float*)d_out;                 // (4,50,300,256) fp32
    dim3 grid(75, 200, 1);                      // 75*4 frames, 200 (b,f) pairs
    acf_kernel<<<grid, 256>>>(in, out);
}

// round 3
// speedup vs baseline: 4.3797x; 1.1034x over previous
#include <cuda_runtime.h>
#include <cuda_bf16.h>

// Register-resident 512-pt FFT (radix 8x8x8): 64 threads/FFT, 8 complex/thread.
// Twiddles from shared tables (built once/block); Hann window from same table.
// Channels packed as one complex signal; power spectra packed as Q = P0 + i*P1.

#define TPI_512 0.012271846303085130f   // 2*pi/512
#define TPI_64  0.098174770424681038f   // 2*pi/64

__device__ __forceinline__ float2 cmul(float2 a, float2 b) {
    return make_float2(fmaf(a.x, b.x, -a.y * b.y), fmaf(a.x, b.y, a.y * b.x));
}
// a * conj(b)
__device__ __forceinline__ float2 cmulc(float2 a, float2 b) {
    return make_float2(fmaf(a.x, b.x, a.y * b.y), fmaf(a.y, b.x, -a.x * b.y));
}
template<int SGN>
__device__ __forceinline__ float2 cmul_t(float2 a, float2 b) {
    return (SGN < 0) ? cmul(a, b) : cmulc(a, b);
}

template<int SGN>   // -1 = forward (e^{-i}), +1 = inverse (e^{+i})
__device__ __forceinline__ void radix8(float2 x[8]) {
    const float C = 0.70710678118654752440f;
    float2 t0 = make_float2(x[0].x + x[4].x, x[0].y + x[4].y);
    float2 t4 = make_float2(x[0].x - x[4].x, x[0].y - x[4].y);
    float2 t1 = make_float2(x[1].x + x[5].x, x[1].y + x[5].y);
    float2 t5 = make_float2(x[1].x - x[5].x, x[1].y - x[5].y);
    float2 t2 = make_float2(x[2].x + x[6].x, x[2].y + x[6].y);
    float2 t6 = make_float2(x[2].x - x[6].x, x[2].y - x[6].y);
    float2 t3 = make_float2(x[3].x + x[7].x, x[3].y + x[7].y);
    float2 t7 = make_float2(x[3].x - x[7].x, x[3].y - x[7].y);
    if (SGN < 0) {
        t5 = make_float2(C * (t5.x + t5.y), C * (t5.y - t5.x));   // * (c - ic)
        t6 = make_float2(t6.y, -t6.x);                            // * -i
        t7 = make_float2(C * (t7.y - t7.x), -C * (t7.x + t7.y));  // * (-c - ic)
    } else {
        t5 = make_float2(C * (t5.x - t5.y), C * (t5.x + t5.y));   // * (c + ic)
        t6 = make_float2(-t6.y, t6.x);                            // * +i
        t7 = make_float2(-C * (t7.x + t7.y), C * (t7.x - t7.y));  // * (-c + ic)
    }
    float2 u0 = make_float2(t0.x + t2.x, t0.y + t2.y);
    float2 u2 = make_float2(t0.x - t2.x, t0.y - t2.y);
    float2 u1 = make_float2(t1.x + t3.x, t1.y + t3.y);
    float2 u3 = make_float2(t1.x - t3.x, t1.y - t3.y);
    u3 = (SGN < 0) ? make_float2(u3.y, -u3.x) : make_float2(-u3.y, u3.x);
    x[0] = make_float2(u0.x + u1.x, u0.y + u1.y);
    x[4] = make_float2(u0.x - u1.x, u0.y - u1.y);
    x[2] = make_float2(u2.x + u3.x, u2.y + u3.y);
    x[6] = make_float2(u2.x - u3.x, u2.y - u3.y);
    float2 v0 = make_float2(t4.x + t6.x, t4.y + t6.y);
    float2 v2 = make_float2(t4.x - t6.x, t4.y - t6.y);
    float2 v1 = make_float2(t5.x + t7.x, t5.y + t7.y);
    float2 v3 = make_float2(t5.x - t7.x, t5.y - t7.y);
    v3 = (SGN < 0) ? make_float2(v3.y, -v3.x) : make_float2(-v3.y, v3.x);
    x[1] = make_float2(v0.x + v1.x, v0.y + v1.y);
    x[5] = make_float2(v0.x - v1.x, v0.y - v1.y);
    x[3] = make_float2(v2.x + v3.x, v2.y + v3.y);
    x[7] = make_float2(v2.x - v3.x, v2.y - v3.y);
}

// Bank-conflict-free swizzled transpose addressing (verified per half-warp).
__device__ __forceinline__ int phys1(int k1, int n2) {
    return (k1 << 6) | (n2 ^ ((k1 & 1) << 3));
}
__device__ __forceinline__ int phys2i(int k1, int k1p, int b) {
    return (k1 << 6) | ((k1p >> 1) << 4) | (((k1 ^ k1p) & 1) << 3) | ((b ^ k1p) & 7);
}
__device__ __forceinline__ int physF(int k) {
    return k ^ (((k >> 4) & 3) << 1);
}

// 512-pt complex FFT across 64 threads. Input: x[r] = data[64r + t].
// Output: x[r] = F[(r<<6) + ((t&7)<<3) + (t>>3)]. 2 internal __syncthreads.
template<int SGN>
__device__ __forceinline__ void fft512(float2 x[8], int t,
                                       float2* bufT1, float2* bufT2,
                                       const float2* __restrict__ W512,
                                       const float2* __restrict__ T2) {
    radix8<SGN>(x);
#pragma unroll
    for (int r = 1; r < 8; r++) x[r] = cmul_t<SGN>(x[r], W512[t * r]);   // t*r <= 441
#pragma unroll
    for (int r = 0; r < 8; r++) bufT1[phys1(r, t)] = x[r];
    __syncthreads();
    const int k1 = t >> 3, b = t & 7;
#pragma unroll
    for (int a = 0; a < 8; a++) x[a] = bufT1[phys1(k1, (a << 3) | b)];
    radix8<SGN>(x);
#pragma unroll
    for (int r = 1; r < 8; r++) x[r] = cmul_t<SGN>(x[r], T2[b * 9 + r]); // w_64^{b*r}
#pragma unroll
    for (int r = 0; r < 8; r++) bufT2[phys2i(k1, r, b)] = x[r];
    __syncthreads();
#pragma unroll
    for (int bb = 0; bb < 8; bb++) x[bb] = bufT2[phys2i(k1, b, bb)];
    radix8<SGN>(x);
}

__global__ void __launch_bounds__(256)
acf_kernel(const float2* __restrict__ in, float* __restrict__ out) {
    __shared__ float2 SM[2][4 * 520];   // ping-pong transpose buffers (4 FFT groups)
    __shared__ float2 W512[512];        // W512[m] = e^{-i 2pi m/512}
    __shared__ float2 T2[72];           // T2[b*9+r] = e^{-i 2pi b*r/64}, padded stride 9

    const int tid   = threadIdx.x;
    const int g     = tid >> 6;        // FFT group 0..3
    const int t     = tid & 63;        // lane within FFT
    const int frame = blockIdx.x * 4 + g;
    const int bf    = blockIdx.y;

    // ---- Build twiddle tables (once per block) ----
    {
        float s, c;
        sincosf(-TPI_512 * (float)tid, &s, &c);
        W512[tid] = make_float2(c, s);
        sincosf(-TPI_512 * (float)(tid + 256), &s, &c);
        W512[tid + 256] = make_float2(c, s);
        if (tid < 72) {
            const int b = tid / 9, r = tid - 9 * b;
            sincosf(-TPI_64 * (float)(b * r), &s, &c);
            T2[tid] = make_float2(c, s);
        }
    }
    __syncthreads();

    float2* smA = &SM[0][g * 520];
    float2* smB = &SM[1][g * 520];

    // Frame start, matching np.linspace(0, 19488, 300).astype(int64).
    const long start = (long)(19488.0 * (double)frame / 299.0);
    const float2* src = in + ((long)bf * 20000 + start);

    // Load + Hann window (window = 0.5*(1 - cos) = 0.5*(1 - W512[n].x)).
    float2 x[8];
#pragma unroll
    for (int r = 0; r < 8; r++) {
        const int n = (r << 6) + t;
        const float w = 0.5f * (1.0f - W512[n].x);
        const float2 v = src[n];
        x[r] = make_float2(v.x * w, v.y * w);
    }

    // Forward FFT. Output: x[r] = F[k], k = 64r + 8*(t&7) + (t>>3).
    fft512<-1>(x, t, smA, smB, W512, T2);

    // Store F at natural k (smA reads finished before last barrier inside fft512).
    const int klo = ((t & 7) << 3) | (t >> 3);
#pragma unroll
    for (int r = 0; r < 8; r++) smA[physF((r << 6) + klo)] = x[r];
    __syncthreads();

    // Hermitian split + power spectra -> Q packed for inverse: x[r] = Q[64r + t].
#pragma unroll
    for (int r = 0; r < 8; r++) {
        const int k  = (r << 6) + t;
        const int kk = (512 - k) & 511;
        const float2 Fk = smA[physF(k)];
        const float2 Fm = smA[physF(kk)];
        const float ax = 0.5f * (Fk.x + Fm.x);
        const float ay = 0.5f * (Fk.y - Fm.y);
        const float bx = 0.5f * (Fk.y + Fm.y);
        const float by = -0.5f * (Fk.x - Fm.x);
        x[r] = make_float2(ax * ax + ay * ay, bx * bx + by * by);
    }

    // Inverse FFT. Output: x[c] = 512 * (acf0 + i*acf1)[n], n = 64c + 8*(t&7) + (t>>3).
    fft512<+1>(x, t, smB, smA, W512, T2);

    // Broadcast acf[0] (held by t==0, reg 0).
    if (t == 0) smB[512] = x[0];
    __syncthreads();

    const float inv = 1.0f / 512.0f;
    const float2 q0 = smB[512];
    const float n0 = fmaxf(q0.x * inv, 0.0f);
    const float n1 = fmaxf(q0.y * inv, 0.0f);
    const float s0 = (n0 == 0.0f) ? 1.0f : rsqrtf(n0);
    const float s1 = (n1 == 0.0f) ? 1.0f : rsqrtf(n1);

    float* op = out + ((long)bf * 300 + frame) * 256;
#pragma unroll
    for (int c = 0; c < 4; c++) {            // lags 0..255 <=> c < 4
        const float a0 = fmaxf(x[c].x * inv, 0.0f) * s0;
        const float a1 = fmaxf(x[c].y * inv, 0.0f) * s1;
        op[(c << 6) + klo] = 0.5f * (a0 + a1);
    }
}

extern "C" void kernel_launch(void* const* d_in, const int* in_sizes, int n_in,
                              void* d_out, int out_size) {
    const float2* in = (const float2*)d_in[0];  // (4,50,20000,2) fp32 as float2
    float* out = (float*)d_out;                 // (4,50,300,256) fp32
    dim3 grid(75, 200, 1);                      // 75*4 frames, 200 (b,f) pairs
    acf_kernel<<<grid, 256>>>(in, out);
}

// round 4
// speedup vs baseline: 4.4230x; 1.0099x over previous
#include <cuda_runtime.h>
#include <cuda_bf16.h>

// Register-resident 512-pt FFT (radix 8x8x8): 64 threads/FFT, 8 complex/thread.
// Conflict-free per-r twiddle subtables, Hann window from twiddle identity,
// per-group named barriers so FFT groups' smem/compute phases overlap.

#define TPI_512 0.012271846303085130f   // 2*pi/512
#define TPI_64  0.098174770424681038f   // 2*pi/64

__device__ __forceinline__ float2 cmul(float2 a, float2 b) {
    return make_float2(fmaf(a.x, b.x, -a.y * b.y), fmaf(a.x, b.y, a.y * b.x));
}
__device__ __forceinline__ float2 cmulc(float2 a, float2 b) {   // a * conj(b)
    return make_float2(fmaf(a.x, b.x, a.y * b.y), fmaf(a.y, b.x, -a.x * b.y));
}
template<int SGN>
__device__ __forceinline__ float2 cmul_t(float2 a, float2 b) {
    return (SGN < 0) ? cmul(a, b) : cmulc(a, b);
}

// Named barrier over one 64-thread FFT group (warps 2g, 2g+1).
__device__ __forceinline__ void gbar(int g) {
    asm volatile("bar.sync %0, 64;" :: "r"(g + 1) : "memory");
}

template<int SGN>   // -1 = forward (e^{-i}), +1 = inverse (e^{+i})
__device__ __forceinline__ void radix8(float2 x[8]) {
    const float C = 0.70710678118654752440f;
    float2 t0 = make_float2(x[0].x + x[4].x, x[0].y + x[4].y);
    float2 t4 = make_float2(x[0].x - x[4].x, x[0].y - x[4].y);
    float2 t1 = make_float2(x[1].x + x[5].x, x[1].y + x[5].y);
    float2 t5 = make_float2(x[1].x - x[5].x, x[1].y - x[5].y);
    float2 t2 = make_float2(x[2].x + x[6].x, x[2].y + x[6].y);
    float2 t6 = make_float2(x[2].x - x[6].x, x[2].y - x[6].y);
    float2 t3 = make_float2(x[3].x + x[7].x, x[3].y + x[7].y);
    float2 t7 = make_float2(x[3].x - x[7].x, x[3].y - x[7].y);
    if (SGN < 0) {
        t5 = make_float2(C * (t5.x + t5.y), C * (t5.y - t5.x));
        t6 = make_float2(t6.y, -t6.x);
        t7 = make_float2(C * (t7.y - t7.x), -C * (t7.x + t7.y));
    } else {
        t5 = make_float2(C * (t5.x - t5.y), C * (t5.x + t5.y));
        t6 = make_float2(-t6.y, t6.x);
        t7 = make_float2(-C * (t7.x + t7.y), C * (t7.x - t7.y));
    }
    float2 u0 = make_float2(t0.x + t2.x, t0.y + t2.y);
    float2 u2 = make_float2(t0.x - t2.x, t0.y - t2.y);
    float2 u1 = make_float2(t1.x + t3.x, t1.y + t3.y);
    float2 u3 = make_float2(t1.x - t3.x, t1.y - t3.y);
    u3 = (SGN < 0) ? make_float2(u3.y, -u3.x) : make_float2(-u3.y, u3.x);
    x[0] = make_float2(u0.x + u1.x, u0.y + u1.y);
    x[4] = make_float2(u0.x - u1.x, u0.y - u1.y);
    x[2] = make_float2(u2.x + u3.x, u2.y + u3.y);
    x[6] = make_float2(u2.x - u3.x, u2.y - u3.y);
    float2 v0 = make_float2(t4.x + t6.x, t4.y + t6.y);
    float2 v2 = make_float2(t4.x - t6.x, t4.y - t6.y);
    float2 v1 = make_float2(t5.x + t7.x, t5.y + t7.y);
    float2 v3 = make_float2(t5.x - t7.x, t5.y - t7.y);
    v3 = (SGN < 0) ? make_float2(v3.y, -v3.x) : make_float2(-v3.y, v3.x);
    x[1] = make_float2(v0.x + v1.x, v0.y + v1.y);
    x[5] = make_float2(v0.x - v1.x, v0.y - v1.y);
    x[3] = make_float2(v2.x + v3.x, v2.y + v3.y);
    x[7] = make_float2(v2.x - v3.x, v2.y - v3.y);
}

// Bank-conflict-free swizzled transpose addressing (verified per half-warp).
__device__ __forceinline__ int phys1(int k1, int n2) {
    return (k1 << 6) | (n2 ^ ((k1 & 1) << 3));
}
__device__ __forceinline__ int phys2i(int k1, int k1p, int b) {
    return (k1 << 6) | ((k1p >> 1) << 4) | (((k1 ^ k1p) & 1) << 3) | ((b ^ k1p) & 7);
}
__device__ __forceinline__ int physF(int k) {
    return k ^ (((k >> 4) & 3) << 1);
}

// 512-pt complex FFT across 64 threads. Input: x[r] = data[64r + t].
// Output: x[r] = F[(r<<6) + ((t&7)<<3) + (t>>3)]. 2 internal group barriers.
template<int SGN>
__device__ __forceinline__ void fft512(float2 x[8], int t, int g,
                                       float2* bufT1, float2* bufT2,
                                       const float2* __restrict__ Wr,
                                       const float2* __restrict__ T2) {
    radix8<SGN>(x);
#pragma unroll
    for (int r = 1; r < 8; r++) x[r] = cmul_t<SGN>(x[r], Wr[((r - 1) << 6) | t]);
#pragma unroll
    for (int r = 0; r < 8; r++) bufT1[phys1(r, t)] = x[r];
    gbar(g);
    const int k1 = t >> 3, b = t & 7;
#pragma unroll
    for (int a = 0; a < 8; a++) x[a] = bufT1[phys1(k1, (a << 3) | b)];
    radix8<SGN>(x);
#pragma unroll
    for (int r = 1; r < 8; r++) x[r] = cmul_t<SGN>(x[r], T2[b * 9 + r]);
#pragma unroll
    for (int r = 0; r < 8; r++) bufT2[phys2i(k1, r, b)] = x[r];
    gbar(g);
#pragma unroll
    for (int bb = 0; bb < 8; bb++) x[bb] = bufT2[phys2i(k1, b, bb)];
    radix8<SGN>(x);
}

__global__ void __launch_bounds__(256)
acf_kernel(const float2* __restrict__ in, float* __restrict__ out) {
    __shared__ float2 SM[2][4 * 520];   // ping-pong transpose buffers (4 FFT groups)
    __shared__ float2 Wr[448];          // Wr[(r-1)*64+t] = e^{-i 2pi r t/512}, r=1..7
    __shared__ float2 T2[72];           // T2[b*9+r] = e^{-i 2pi b r/64}, padded stride 9

    const int tid   = threadIdx.x;
    const int g     = tid >> 6;        // FFT group 0..3
    const int t     = tid & 63;        // lane within FFT
    const int frame = blockIdx.x * 4 + g;
    const int bf    = blockIdx.y;

    // ---- Build twiddle tables (once per block) ----
    {
        float s, c;
        for (int i = tid; i < 448; i += 256) {
            const int r = (i >> 6) + 1, tt = i & 63;
            sincosf(-TPI_512 * (float)(r * tt), &s, &c);
            Wr[i] = make_float2(c, s);
        }
        if (tid < 72) {
            const int b = tid / 9, r = tid - 9 * b;
            sincosf(-TPI_64 * (float)(b * r), &s, &c);
            T2[tid] = make_float2(c, s);
        }
    }
    __syncthreads();   // tables visible to all groups; only block-wide sync

    float2* smA = &SM[0][g * 520];
    float2* smB = &SM[1][g * 520];

    // Frame start, matching np.linspace(0, 19488, 300).astype(int64).
    const long start = (long)(19488.0 * (double)frame / 299.0);
    const float2* src = in + ((long)bf * 20000 + start);

    // Load + Hann window. cos(2pi(64r+t)/512) = ca_r*W1.x + sa_r*W1.y,
    // with W1 = Wr[t] = e^{-i 2pi t/512}; ca_r = cos(pi r/4), sa_r = sin(pi r/4).
    float2 x[8];
    {
        const float2 w1 = Wr[t];
        const float CQ = 0.70710678118654752440f;
        const float ca[8] = {1.0f,  CQ, 0.0f, -CQ, -1.0f, -CQ, 0.0f,  CQ};
        const float sa[8] = {0.0f,  CQ, 1.0f,  CQ,  0.0f, -CQ, -1.0f, -CQ};
#pragma unroll
        for (int r = 0; r < 8; r++) {
            const float cosn = ca[r] * w1.x + sa[r] * w1.y;
            const float w = 0.5f - 0.5f * cosn;
            const float2 v = src[(r << 6) + t];
            x[r] = make_float2(v.x * w, v.y * w);
        }
    }

    // Forward FFT. Output: x[r] = F[k], k = 64r + 8*(t&7) + (t>>3).
    fft512<-1>(x, t, g, smA, smB, Wr, T2);

    // Store F at natural k.
    const int klo = ((t & 7) << 3) | (t >> 3);
#pragma unroll
    for (int r = 0; r < 8; r++) smA[physF((r << 6) + klo)] = x[r];
    gbar(g);

    // Hermitian split + power spectra -> Q packed for inverse: x[r] = Q[64r + t].
#pragma unroll
    for (int r = 0; r < 8; r++) {
        const int k  = (r << 6) + t;
        const int kk = (512 - k) & 511;
        const float2 Fk = smA[physF(k)];
        const float2 Fm = smA[physF(kk)];
        const float ax = 0.5f * (Fk.x + Fm.x);
        const float ay = 0.5f * (Fk.y - Fm.y);
        const float bx = 0.5f * (Fk.y + Fm.y);
        const float by = -0.5f * (Fk.x - Fm.x);
        x[r] = make_float2(ax * ax + ay * ay, bx * bx + by * by);
    }

    // Inverse FFT. Output: x[c] = 512 * (acf0 + i*acf1)[n], n = 64c + 8*(t&7) + (t>>3).
    fft512<+1>(x, t, g, smB, smA, Wr, T2);

    // Broadcast acf[0] (held by t==0, reg 0).
    if (t == 0) smB[512] = x[0];
    gbar(g);

    const float inv = 1.0f / 512.0f;
    const float2 q0 = smB[512];
    const float n0 = fmaxf(q0.x * inv, 0.0f);
    const float n1 = fmaxf(q0.y * inv, 0.0f);
    const float s0 = (n0 == 0.0f) ? 1.0f : rsqrtf(n0);
    const float s1 = (n1 == 0.0f) ? 1.0f : rsqrtf(n1);

    float* op = out + ((long)bf * 300 + frame) * 256;
#pragma unroll
    for (int c = 0; c < 4; c++) {            // lags 0..255 <=> c < 4
        const float a0 = fmaxf(x[c].x * inv, 0.0f) * s0;
        const float a1 = fmaxf(x[c].y * inv, 0.0f) * s1;
        op[(c << 6) + klo] = 0.5f * (a0 + a1);
    }
}

extern "C" void kernel_launch(void* const* d_in, const int* in_sizes, int n_in,
                              void* d_out, int out_size) {
    const float2* in = (const float2*)d_in[0];  // (4,50,20000,2) fp32 as float2
    float* out = (float*)d_out;                 // (4,50,300,256) fp32
    dim3 grid(75, 200, 1);                      // 75*4 frames, 200 (b,f) pairs
    acf_kernel<<<grid, 256>>>(in, out);
}

// round 5
// speedup vs baseline: 5.2663x; 1.1907x over previous
#include <cuda_runtime.h>
#include <cuda_bf16.h>

// Register-resident 512-pt FFT (radix 8x8x8): 64 threads/FFT, 8 complex/thread.
// Packed f32x2 butterflies, compile-time twiddle tables, per-group named barriers.

typedef unsigned long long ull;

// ---------- compile-time twiddle tables ----------
struct TwTab { float2 w[520]; };   // [0,448): Wr[(r-1)*64+t] = e^{-i2pi r t/512}
                                   // [448,520): T2[b*9+r]    = e^{-i2pi b r/64}
constexpr double TPI_D = 6.283185307179586476925286766559;
constexpr double tsin(double x) {
    double x2 = x * x, t = x, s = x;
    for (int k = 1; k <= 13; k++) { t = -t * x2 / ((2.0 * k) * (2.0 * k + 1.0)); s += t; }
    return s;
}
constexpr double tcos(double x) {
    double x2 = x * x, t = 1.0, s = 1.0;
    for (int k = 1; k <= 13; k++) { t = -t * x2 / ((2.0 * k - 1.0) * (2.0 * k)); s += t; }
    return s;
}
constexpr TwTab make_tab() {
    TwTab T{};
    for (int r = 1; r < 8; r++)
        for (int t = 0; t < 64; t++) {
            int m = (r * t) & 511; int mm = (m > 256) ? m - 512 : m;
            double a = -TPI_D * (double)mm / 512.0;
            T.w[(r - 1) * 64 + t].x = (float)tcos(a);
            T.w[(r - 1) * 64 + t].y = (float)tsin(a);
        }
    for (int b = 0; b < 8; b++)
        for (int r = 0; r < 9; r++) {
            int m = (b * (r & 7)) & 63; int mm = (m > 32) ? m - 64 : m;
            double a = -TPI_D * (double)mm / 64.0;
            T.w[448 + b * 9 + r].x = (float)tcos(a);
            T.w[448 + b * 9 + r].y = (float)tsin(a);
        }
    return T;
}
__device__ constexpr TwTab d_tw = make_tab();

// ---------- packed f32x2 helpers ----------
__device__ __forceinline__ ull PK2(float x, float y) {
    ull r; asm("mov.b64 %0, {%1, %2};" : "=l"(r) : "f"(x), "f"(y)); return r;
}
__device__ __forceinline__ void UPK(ull v, float& x, float& y) {
    asm("mov.b64 {%0, %1}, %2;" : "=f"(x), "=f"(y) : "l"(v));
}
__device__ __forceinline__ ull SWP(ull v) { float x, y; UPK(v, x, y); return PK2(y, x); }
__device__ __forceinline__ ull padd(ull a, ull b) {
    ull r; asm("add.rn.f32x2 %0, %1, %2;" : "=l"(r) : "l"(a), "l"(b)); return r;
}
__device__ __forceinline__ ull pmul(ull a, ull b) {
    ull r; asm("mul.rn.f32x2 %0, %1, %2;" : "=l"(r) : "l"(a), "l"(b)); return r;
}
__device__ __forceinline__ ull pfma(ull a, ull b, ull c) {
    ull r; asm("fma.rn.f32x2 %0, %1, %2, %3;" : "=l"(r) : "l"(a), "l"(b), "l"(c)); return r;
}

// Named barrier over one 64-thread FFT group (warps 2g, 2g+1).
__device__ __forceinline__ void gbar(int g) {
    asm volatile("bar.sync %0, 64;" :: "r"(g + 1) : "memory");
}

// ---------- packed radix-8 butterfly (verified lane-by-lane, both signs) ----------
template<int SGN>   // -1 = forward (e^{-i}), +1 = inverse (e^{+i})
__device__ __forceinline__ void radix8p(ull x[8]) {
    const ull NEG1 = PK2(-1.0f, -1.0f);
    const ull PM   = PK2( 1.0f, -1.0f);
    const ull MP   = PK2(-1.0f,  1.0f);
    const float Cq = 0.70710678118654752440f;
    const ull CC   = PK2(Cq, Cq);
    ull t0 = padd(x[0], x[4]), t4 = pfma(x[4], NEG1, x[0]);
    ull t1 = padd(x[1], x[5]), t5 = pfma(x[5], NEG1, x[1]);
    ull t2 = padd(x[2], x[6]), t6 = pfma(x[6], NEG1, x[2]);
    ull t3 = padd(x[3], x[7]), t7 = pfma(x[7], NEG1, x[3]);
    ull s5 = SWP(t5), s6 = SWP(t6), s7 = SWP(t7);
    ull t5r, t7r;
    if (SGN < 0) {
        t5r = pmul(pfma(s5, PM, t5), CC);               // (C(x+y), C(y-x))
        t7r = pmul(pfma(t7, NEG1, pmul(s7, PM)), CC);   // (C(y-x), -C(x+y))
    } else {
        t5r = pmul(pfma(s5, MP, t5), CC);               // (C(x-y), C(x+y))
        t7r = pmul(pfma(t7, NEG1, pmul(s7, MP)), CC);   // (-C(x+y), C(x-y))
    }
    ull u0 = padd(t0, t2), u2 = pfma(t2, NEG1, t0);
    ull u1 = padd(t1, t3), u3 = pfma(t3, NEG1, t1);
    ull v0, v2;
    if (SGN < 0) { v0 = pfma(s6, PM, t4); v2 = pfma(s6, MP, t4); }   // t6 * -i
    else         { v0 = pfma(s6, MP, t4); v2 = pfma(s6, PM, t4); }   // t6 * +i
    ull v1 = padd(t5r, t7r), v3 = pfma(t7r, NEG1, t5r);
    x[0] = padd(u0, u1); x[4] = pfma(u1, NEG1, u0);
    x[1] = padd(v0, v1); x[5] = pfma(v1, NEG1, v0);
    ull su3 = SWP(u3), sv3 = SWP(v3);
    if (SGN < 0) {
        x[2] = pfma(su3, PM, u2); x[6] = pfma(su3, MP, u2);
        x[3] = pfma(sv3, PM, v2); x[7] = pfma(sv3, MP, v2);
    } else {
        x[2] = pfma(su3, MP, u2); x[6] = pfma(su3, PM, u2);
        x[3] = pfma(sv3, MP, v2); x[7] = pfma(sv3, PM, v2);
    }
}

// Scalar complex twiddle on a packed value: a * w (SGN<0) or a * conj(w) (SGN>0).
template<int SGN>
__device__ __forceinline__ float2 twid(ull a, float2 w) {
    float ax, ay; UPK(a, ax, ay);
    float2 r;
    if (SGN < 0) { r.x = fmaf(ax, w.x, -ay * w.y); r.y = fmaf(ax, w.y,  ay * w.x); }
    else         { r.x = fmaf(ax, w.x,  ay * w.y); r.y = fmaf(ay, w.x, -ax * w.y); }
    return r;
}

// Bank-conflict-free swizzled transpose addressing (verified per half-warp).
__device__ __forceinline__ int phys1(int k1, int n2) {
    return (k1 << 6) | (n2 ^ ((k1 & 1) << 3));
}
__device__ __forceinline__ int phys2i(int k1, int k1p, int b) {
    return (k1 << 6) | ((k1p >> 1) << 4) | (((k1 ^ k1p) & 1) << 3) | ((b ^ k1p) & 7);
}
__device__ __forceinline__ int physF(int k) {
    return k ^ (((k >> 4) & 3) << 1);
}

// 512-pt complex FFT across 64 threads. Input: x[r] = data[64r + t] (packed).
// Output: x[r] = F[(r<<6) + ((t&7)<<3) + (t>>3)]. 2 internal group barriers.
template<int SGN>
__device__ __forceinline__ void fft512(ull x[8], int t, int g,
                                       float2* bufT1, float2* bufT2,
                                       const float2* __restrict__ Wr,
                                       const float2* __restrict__ T2) {
    radix8p<SGN>(x);
    bufT1[phys1(0, t)] = twid<SGN>(x[0], make_float2(1.0f, 0.0f));
#pragma unroll
    for (int r = 1; r < 8; r++) bufT1[phys1(r, t)] = twid<SGN>(x[r], Wr[((r - 1) << 6) | t]);
    gbar(g);
    const int k1 = t >> 3, b = t & 7;
    const ull* T1u = (const ull*)bufT1;
#pragma unroll
    for (int a = 0; a < 8; a++) x[a] = T1u[phys1(k1, (a << 3) | b)];
    radix8p<SGN>(x);
    { float xx, yy; UPK(x[0], xx, yy); bufT2[phys2i(k1, 0, b)] = make_float2(xx, yy); }
#pragma unroll
    for (int r = 1; r < 8; r++) bufT2[phys2i(k1, r, b)] = twid<SGN>(x[r], T2[b * 9 + r]);
    gbar(g);
    const ull* T2u = (const ull*)bufT2;
#pragma unroll
    for (int bb = 0; bb < 8; bb++) x[bb] = T2u[phys2i(k1, b, bb)];
    radix8p<SGN>(x);
}

__global__ void __launch_bounds__(256)
acf_kernel(const float2* __restrict__ in, float* __restrict__ out) {
    __shared__ float2 SM[2][4 * 520];   // ping-pong transpose buffers (4 FFT groups)
    __shared__ float2 TAB[520];         // Wr (448) + T2 (72)

    const int tid   = threadIdx.x;
    const int g     = tid >> 6;        // FFT group 0..3
    const int t     = tid & 63;        // lane within FFT
    const int frame = blockIdx.x * 4 + g;
    const int bf    = blockIdx.y;

    // Copy twiddle tables from gmem (L2-resident after first wave).
    for (int i = tid; i < 520; i += 256) TAB[i] = d_tw.w[i];
    __syncthreads();
    const float2* Wr = TAB;
    const float2* T2 = TAB + 448;

    float2* smA = &SM[0][g * 520];
    float2* smB = &SM[1][g * 520];

    // Frame start: exact int match of np.linspace(0,19488,300).astype(int64).
    const int start = (19488 * frame) / 299;
    const ull* src = (const ull*)(in + ((long)bf * 20000 + start));

    // Load + Hann window. cos(2pi(64r+t)/512) = ca_r*w1.x + sa_r*w1.y.
    ull x[8];
    {
        const float2 w1 = Wr[t];   // e^{-i 2pi t/512}
        const float CQ = 0.70710678118654752440f;
        const float ca[8] = {1.0f,  CQ, 0.0f, -CQ, -1.0f, -CQ,  0.0f,  CQ};
        const float sa[8] = {0.0f,  CQ, 1.0f,  CQ,  0.0f, -CQ, -1.0f, -CQ};
#pragma unroll
        for (int r = 0; r < 8; r++) {
            const float cosn = ca[r] * w1.x + sa[r] * w1.y;
            const float w = 0.5f - 0.5f * cosn;
            x[r] = pmul(src[(r << 6) + t], PK2(w, w));
        }
    }

    // Forward FFT. Output: x[r] = F[k], k = 64r + 8*(t&7) + (t>>3).
    fft512<-1>(x, t, g, smA, smB, Wr, T2);

    // Store F at natural k (swizzled).
    const int klo = ((t & 7) << 3) | (t >> 3);
    ull* smAu = (ull*)smA;
#pragma unroll
    for (int r = 0; r < 8; r++) smAu[physF((r << 6) + klo)] = x[r];
    gbar(g);

    // Hermitian split + power spectra (packed): S=Fk+Fm, D=Fk-Fm,
    // (p0,p1) = 0.25*(S*S + swap(D*D)).  x[r] = Q[64r + t].
    {
        const ull NEG1 = PK2(-1.0f, -1.0f);
        const ull QQ   = PK2(0.25f, 0.25f);
#pragma unroll
        for (int r = 0; r < 8; r++) {
            const int k  = (r << 6) + t;
            const int kk = (512 - k) & 511;
            const ull Fk = smAu[physF(k)];
            const ull Fm = smAu[physF(kk)];
            const ull S = padd(Fk, Fm);
            const ull D = pfma(Fm, NEG1, Fk);
            x[r] = pmul(padd(pmul(S, S), SWP(pmul(D, D))), QQ);
        }
    }

    // Inverse FFT. Output: x[c] = 512*(acf0 + i*acf1)[n], n = 64c + 8*(t&7) + (t>>3).
    fft512<+1>(x, t, g, smB, smA, Wr, T2);

    // Broadcast acf[0] (held by t==0, reg 0).
    if (t == 0) *(ull*)&smB[512] = x[0];
    gbar(g);

    const float inv = 1.0f / 512.0f;
    const float2 q0 = smB[512];
    const float n0 = fmaxf(q0.x * inv, 0.0f);
    const float n1 = fmaxf(q0.y * inv, 0.0f);
    const float s0 = (n0 == 0.0f) ? 1.0f : rsqrtf(n0);
    const float s1 = (n1 == 0.0f) ? 1.0f : rsqrtf(n1);

    float* op = out + ((long)bf * 300 + frame) * 256;
#pragma unroll
    for (int c = 0; c < 4; c++) {            // lags 0..255 <=> c < 4
        float qx, qy; UPK(x[c], qx, qy);
        const float a0 = fmaxf(qx * inv, 0.0f) * s0;
        const float a1 = fmaxf(qy * inv, 0.0f) * s1;
        op[(c << 6) + klo] = 0.5f * (a0 + a1);
    }
}

extern "C" void kernel_launch(void* const* d_in, const int* in_sizes, int n_in,
                              void* d_out, int out_size) {
    const float2* in = (const float2*)d_in[0];  // (4,50,20000,2) fp32 as float2
    float* out = (float*)d_out;                 // (4,50,300,256) fp32
    dim3 grid(75, 200, 1);                      // 75*4 frames, 200 (b,f) pairs
    acf_kernel<<<grid, 256>>>(in, out);
}